// round 4
// baseline (speedup 1.0000x reference)
#include <cuda_runtime.h>
#include <cuda_bf16.h>
#include <math.h>
#include <stdint.h>

#define S_     2048
#define E_     2048
#define NH     32
#define NG     8
#define DH     64
#define QKV_N  3072   /* (H + 2G) * D */
#define SW_    128
#define TQ     32

// ---------------- scratch (__device__ globals; no allocs allowed) ----------
__device__ float g_qkv[(size_t)S_ * QKV_N];
__device__ float g_ctx[(size_t)S_ * E_];
__device__ __nv_bfloat16 g_xhi[(size_t)S_ * E_],     g_xlo[(size_t)S_ * E_];
__device__ __nv_bfloat16 g_wqhi[(size_t)QKV_N * E_], g_wqlo[(size_t)QKV_N * E_];
__device__ __nv_bfloat16 g_wohi[(size_t)E_ * E_],    g_wolo[(size_t)E_ * E_];
__device__ __nv_bfloat16 g_chi[(size_t)S_ * E_],     g_clo[(size_t)S_ * E_];

// ---------------- helpers --------------------------------------------------
__device__ __forceinline__ uint32_t smem_u32(const void* p) {
    return (uint32_t)__cvta_generic_to_shared(p);
}
__device__ __forceinline__ void cp16(uint32_t dst, const void* src) {
    asm volatile("cp.async.cg.shared.global [%0], [%1], 16;"
                 :: "r"(dst), "l"(src) : "memory");
}
__device__ __forceinline__ void ldm_x4(uint32_t* r, uint32_t addr) {
    asm volatile("ldmatrix.sync.aligned.m8n8.x4.shared.b16 {%0,%1,%2,%3}, [%4];"
                 : "=r"(r[0]), "=r"(r[1]), "=r"(r[2]), "=r"(r[3]) : "r"(addr));
}
__device__ __forceinline__ void mma_bf16(float* c, const uint32_t* a,
                                         uint32_t b0, uint32_t b1) {
    asm volatile(
        "mma.sync.aligned.m16n8k16.row.col.f32.bf16.bf16.f32 "
        "{%0,%1,%2,%3},{%4,%5,%6,%7},{%8,%9},{%0,%1,%2,%3};"
        : "+f"(c[0]), "+f"(c[1]), "+f"(c[2]), "+f"(c[3])
        : "r"(a[0]), "r"(a[1]), "r"(a[2]), "r"(a[3]), "r"(b0), "r"(b1));
}

// ---------------- fp32 -> (hi, lo) bf16 split ------------------------------
__global__ __launch_bounds__(256)
void conv_hilo(const float* __restrict__ src,
               __nv_bfloat16* __restrict__ hi,
               __nv_bfloat16* __restrict__ lo, int n4)
{
    int i = blockIdx.x * 256 + threadIdx.x;
    if (i >= n4) return;
    float4 v = ((const float4*)src)[i];
    float f[4] = {v.x, v.y, v.z, v.w};
    __nv_bfloat16 h[4], l[4];
    #pragma unroll
    for (int k = 0; k < 4; k++) {
        h[k] = __float2bfloat16(f[k]);
        l[k] = __float2bfloat16(f[k] - __bfloat162float(h[k]));
    }
    __nv_bfloat162* hp = (__nv_bfloat162*)hi;
    __nv_bfloat162* lp = (__nv_bfloat162*)lo;
    hp[2*i]   = __nv_bfloat162(h[0], h[1]);
    hp[2*i+1] = __nv_bfloat162(h[2], h[3]);
    lp[2*i]   = __nv_bfloat162(l[0], l[1]);
    lp[2*i+1] = __nv_bfloat162(l[2], l[3]);
}

// ---------------------------------------------------------------------------
// HMMA split-bf16 GEMM: 128x128 CTA, BK=32, 3-stage cp.async, 2 CTAs/SM.
// ---------------------------------------------------------------------------
#define STAGES     3
#define STAGE_B    32768
#define GEMM_SMEM  (STAGES * STAGE_B)

__global__ __launch_bounds__(256, 2)
void gemm_mma(int M, int N, int K,
              const __nv_bfloat16* __restrict__ Ahi,
              const __nv_bfloat16* __restrict__ Alo,
              const __nv_bfloat16* __restrict__ Bhi,
              const __nv_bfloat16* __restrict__ Blo,
              const float* __restrict__ bias,
              float* __restrict__ C)
{
    extern __shared__ char smem[];
    const uint32_t sbase = smem_u32(smem);
    const int tid  = threadIdx.x;
    const int wid  = tid >> 5, lane = tid & 31;
    const int bm   = blockIdx.y * 128, bn = blockIdx.x * 128;
    const int mi   = (wid >> 2) * 64;   // warp m offset
    const int ni   = (wid & 3) * 32;    // warp n offset
    const int NC   = K >> 5;            // chunks of 32

    auto load_chunk = [&](int kc, int st) {
        const __nv_bfloat16* srcs[4] = {Ahi, Alo, Bhi, Blo};
        const int r0s[4] = {bm, bm, bn, bn};
        uint32_t stb = sbase + st * STAGE_B;
        #pragma unroll
        for (int t4 = 0; t4 < 4; t4++) {
            #pragma unroll
            for (int rep = 0; rep < 2; rep++) {
                int idx  = tid + rep * 256;
                int r    = idx >> 2, slot = idx & 3;
                const void* src = srcs[t4] + (size_t)(r0s[t4] + r) * K + kc * 32 + slot * 8;
                uint32_t dst = stb + t4 * 8192 + r * 64 + 16 * (slot ^ ((r >> 1) & 3));
                cp16(dst, src);
            }
        }
        asm volatile("cp.async.commit_group;" ::: "memory");
    };

    float acc[4][4][4];
    #pragma unroll
    for (int i2 = 0; i2 < 4; i2++)
        #pragma unroll
        for (int j = 0; j < 4; j++)
            #pragma unroll
            for (int q = 0; q < 4; q++) acc[i2][j][q] = 0.f;

    load_chunk(0, 0);
    load_chunk(1, 1);

    for (int c = 0; c < NC; ++c) {
        asm volatile("cp.async.wait_group 1;" ::: "memory");
        __syncthreads();
        if (c + 2 < NC) load_chunk(c + 2, (c + 2) % 3);

        uint32_t stb = sbase + (c % 3) * STAGE_B;
        #pragma unroll
        for (int ks = 0; ks < 2; ks++) {
            uint32_t ah[4][4], al[4][4];
            #pragma unroll
            for (int i2 = 0; i2 < 4; i2++) {
                int r    = mi + i2 * 16 + (lane & 15);
                int slot = ks * 2 + (lane >> 4);
                uint32_t off = (uint32_t)(r * 64 + 16 * (slot ^ ((r >> 1) & 3)));
                ldm_x4(ah[i2], stb + 0    + off);
                ldm_x4(al[i2], stb + 8192 + off);
            }
            uint32_t bh[2][4], bl[2][4];
            #pragma unroll
            for (int jp = 0; jp < 2; jp++) {
                int r    = ni + jp * 16 + (lane & 15);
                int slot = ks * 2 + (lane >> 4);
                uint32_t off = (uint32_t)(r * 64 + 16 * (slot ^ ((r >> 1) & 3)));
                ldm_x4(bh[jp], stb + 16384 + off);
                ldm_x4(bl[jp], stb + 24576 + off);
            }
            #pragma unroll
            for (int i2 = 0; i2 < 4; i2++)
                #pragma unroll
                for (int jp = 0; jp < 2; jp++)
                    #pragma unroll
                    for (int sub = 0; sub < 2; sub++) {
                        float* cc = acc[i2][jp * 2 + sub];
                        mma_bf16(cc, ah[i2], bh[jp][sub], bh[jp][sub + 2]);
                        mma_bf16(cc, ah[i2], bl[jp][sub], bl[jp][sub + 2]);
                        mma_bf16(cc, al[i2], bh[jp][sub], bh[jp][sub + 2]);
                    }
        }
    }

    // epilogue: direct stores + bias
    const int row_l = lane >> 2, colq = (lane & 3) * 2;
    #pragma unroll
    for (int i2 = 0; i2 < 4; i2++) {
        int r0 = bm + mi + i2 * 16 + row_l;
        #pragma unroll
        for (int j = 0; j < 4; j++) {
            int cn = bn + ni + j * 8 + colq;
            float b0 = bias[cn], b1 = bias[cn + 1];
            float* cc = acc[i2][j];
            *(float2*)&C[(size_t)r0 * N + cn]       = make_float2(cc[0] + b0, cc[1] + b1);
            *(float2*)&C[(size_t)(r0 + 8) * N + cn] = make_float2(cc[2] + b0, cc[3] + b1);
        }
    }
}

// ---------------------------------------------------------------------------
// YaRN RoPE in-place on Q (heads 0..31) and K (heads 32..39) in g_qkv.
// ---------------------------------------------------------------------------
__global__ void rope_kernel(const int* __restrict__ pos_ids)
{
    const int i  = blockIdx.x;
    const int hh = blockIdx.y;
    const int k  = threadIdx.x;

    float freq = powf(10000.0f, -((float)(2 * k) / 64.0f));
    float wl   = 6.283185307179586f / freq;
    float t    = (wl - 128.0f) / (4096.0f - 128.0f);
    t = fminf(fmaxf(t, 0.0f), 1.0f);
    float eff  = freq * (1.0f - t) + (freq * 0.5f) * t;
    float conc = 0.1f * logf(2.0f) + 1.0f;
    float ang  = (float)pos_ids[i] * eff * conc;
    float sv = sinf(ang), cv = cosf(ang);

    float* p = g_qkv + (size_t)i * QKV_N + hh * DH;
    float x1 = p[k], x2 = p[k + 32];
    p[k]      = x1 * cv - x2 * sv;
    p[k + 32] = x2 * cv + x1 * sv;
}

// ---------------------------------------------------------------------------
// Windowed attention with sink. One block = (32-query tile, kv-group g).
// K/V window (<=159 keys) staged once, reused by 32 queries x 4 heads.
// ---------------------------------------------------------------------------
#define ATT_SMEM_FLOATS (4*32*66 + 160*65 + 160*68 + 32*168 + 64)
#define ATT_SMEM_BYTES  (ATT_SMEM_FLOATS * 4)

__global__ __launch_bounds__(256)
void attn_kernel(const float* __restrict__ sinks)
{
    extern __shared__ float sm[];
    float* Qs = sm;                    // [4][32][66]
    float* Ks = Qs + 4 * 32 * 66;      // [160][65]
    float* Vs = Ks + 160 * 65;         // [160][68]
    float* sc = Vs + 160 * 68;         // [32][168]
    float* mr = sc + 32 * 168;         // [32]
    float* ir = mr + 32;               // [32]

    const int qt = blockIdx.x, g = blockIdx.y;
    const int tid = threadIdx.x;
    const int w = tid >> 5, l = tid & 31;

    const int q0 = qt * TQ;
    const int j0 = max(0, q0 - (SW_ - 1));
    const int nk = q0 + TQ - j0;       // <= 159

    // stage Q (4 heads x 32 q x 64 d)
    for (int e = tid; e < 4 * TQ * 64; e += 256) {
        int h = e >> 11, r = (e >> 6) & 31, d = e & 63;
        Qs[(h * 32 + r) * 66 + d] =
            g_qkv[(size_t)(q0 + r) * QKV_N + (g * 4 + h) * DH + d];
    }
    // stage K and V windows
    for (int e = tid; e < nk * 64; e += 256) {
        int j = e >> 6, d = e & 63;
        Ks[j * 65 + d] = g_qkv[(size_t)(j0 + j) * QKV_N + (NH + g) * DH + d];
        Vs[j * 68 + d] = g_qkv[(size_t)(j0 + j) * QKV_N + (NH + NG + g) * DH + d];
    }
    __syncthreads();

    const int qq = tid >> 3, ts = tid & 7;
    const int iq = q0 + qq;
    const int d0 = ts * 8;

    for (int h = 0; h < 4; h++) {
        const float sink = sinks[g * 4 + h];
        const float* Qr = &Qs[(h * 32 + qq) * 66];

        // scores for this head: thread (qq, ts) covers keys ts, ts+8, ...
        for (int k = ts; k < nk; k += 8) {
            int j = j0 + k;
            const float* Kr = &Ks[k * 65];
            float a0 = 0.f, a1 = 0.f, a2 = 0.f, a3 = 0.f;
            #pragma unroll
            for (int d = 0; d < 64; d += 4) {
                a0 += Qr[d]     * Kr[d];
                a1 += Qr[d + 1] * Kr[d + 1];
                a2 += Qr[d + 2] * Kr[d + 2];
                a3 += Qr[d + 3] * Kr[d + 3];
            }
            bool valid = (j <= iq) && (j >= iq - (SW_ - 1));
            sc[qq * 168 + k] = valid ? (a0 + a1 + a2 + a3) * 0.125f : -INFINITY;
        }
        __syncthreads();

        // warp w reduces rows 4w..4w+3: max
        #pragma unroll
        for (int rr = 0; rr < 4; rr++) {
            int r = w * 4 + rr;
            float m = -INFINITY;
            for (int k = l; k < nk; k += 32) m = fmaxf(m, sc[r * 168 + k]);
            #pragma unroll
            for (int off = 16; off > 0; off >>= 1)
                m = fmaxf(m, __shfl_xor_sync(0xffffffffu, m, off));
            if (l == 0) mr[r] = fmaxf(m, sink);
        }
        __syncthreads();

        // exp in place + sum
        #pragma unroll
        for (int rr = 0; rr < 4; rr++) {
            int r = w * 4 + rr;
            float m = mr[r], s = 0.f;
            for (int k = l; k < nk; k += 32) {
                float p = __expf(sc[r * 168 + k] - m);
                sc[r * 168 + k] = p;
                s += p;
            }
            #pragma unroll
            for (int off = 16; off > 0; off >>= 1)
                s += __shfl_xor_sync(0xffffffffu, s, off);
            if (l == 0) ir[r] = 1.f / (s + __expf(sink - m));
        }
        __syncthreads();

        // AV: thread (qq, ts) computes d0..d0+7
        float acc[8] = {0.f, 0.f, 0.f, 0.f, 0.f, 0.f, 0.f, 0.f};
        for (int k = 0; k < nk; k++) {
            float p = sc[qq * 168 + k];
            const float* Vr = &Vs[k * 68 + d0];
            #pragma unroll
            for (int dd = 0; dd < 8; dd++) acc[dd] += p * Vr[dd];
        }
        float inv = ir[qq];
        #pragma unroll
        for (int dd = 0; dd < 8; dd++)
            g_ctx[(size_t)iq * E_ + (g * 4 + h) * DH + d0 + dd] = acc[dd] * inv;
        __syncthreads();
    }
}

// ---------------------------------------------------------------------------
extern "C" void kernel_launch(void* const* d_in, const int* in_sizes, int n_in,
                              void* d_out, int out_size)
{
    const float* x     = (const float*)d_in[0];
    const int*   pos   = (const int*)  d_in[1];
    const float* Wqkv  = (const float*)d_in[3];
    const float* bqkv  = (const float*)d_in[4];
    const float* Wout  = (const float*)d_in[5];
    const float* bout  = (const float*)d_in[6];
    const float* sinks = (const float*)d_in[7];
    float* out = (float*)d_out;

    float *qkv_p = nullptr, *ctx_p = nullptr;
    __nv_bfloat16 *xhi, *xlo, *wqhi, *wqlo, *wohi, *wolo, *chi, *clo;
    cudaGetSymbolAddress((void**)&qkv_p, g_qkv);
    cudaGetSymbolAddress((void**)&ctx_p, g_ctx);
    cudaGetSymbolAddress((void**)&xhi,  g_xhi);  cudaGetSymbolAddress((void**)&xlo,  g_xlo);
    cudaGetSymbolAddress((void**)&wqhi, g_wqhi); cudaGetSymbolAddress((void**)&wqlo, g_wqlo);
    cudaGetSymbolAddress((void**)&wohi, g_wohi); cudaGetSymbolAddress((void**)&wolo, g_wolo);
    cudaGetSymbolAddress((void**)&chi,  g_chi);  cudaGetSymbolAddress((void**)&clo,  g_clo);

    cudaFuncSetAttribute(gemm_mma, cudaFuncAttributeMaxDynamicSharedMemorySize, GEMM_SMEM);
    cudaFuncSetAttribute(attn_kernel, cudaFuncAttributeMaxDynamicSharedMemorySize, ATT_SMEM_BYTES);

    // 0) split inputs into bf16 hi/lo
    {
        int n4 = (S_ * E_) / 4;
        conv_hilo<<<(n4 + 255) / 256, 256>>>(x, xhi, xlo, n4);
        n4 = (QKV_N * E_) / 4;
        conv_hilo<<<(n4 + 255) / 256, 256>>>(Wqkv, wqhi, wqlo, n4);
        n4 = (E_ * E_) / 4;
        conv_hilo<<<(n4 + 255) / 256, 256>>>(Wout, wohi, wolo, n4);
    }

    // 1) qkv = x @ Wqkv^T + bqkv
    gemm_mma<<<dim3(QKV_N / 128, S_ / 128), 256, GEMM_SMEM>>>(
        S_, QKV_N, E_, xhi, xlo, wqhi, wqlo, bqkv, qkv_p);

    // 2) RoPE
    rope_kernel<<<dim3(S_, NH + NG), 32>>>(pos);

    // 3) windowed sink attention (query-tiled, grouped)
    attn_kernel<<<dim3(S_ / TQ, NG), 256, ATT_SMEM_BYTES>>>(sinks);

    // 4) ctx -> bf16 hi/lo, then out = ctx @ Wout^T + bout
    {
        int n4 = (S_ * E_) / 4;
        conv_hilo<<<(n4 + 255) / 256, 256>>>(ctx_p, chi, clo, n4);
    }
    gemm_mma<<<dim3(E_ / 128, S_ / 128), 256, GEMM_SMEM>>>(
        S_, E_, E_, chi, clo, wohi, wolo, bout, out);
}

// round 5
// speedup vs baseline: 1.1776x; 1.1776x over previous
#include <cuda_runtime.h>
#include <cuda_bf16.h>
#include <math.h>
#include <stdint.h>

#define S_     2048
#define E_     2048
#define NH     32
#define NG     8
#define DH     64
#define QKV_N  3072   /* (H + 2G) * D */
#define SW_    128

// ---------------- scratch (__device__ globals; no allocs allowed) ----------
__device__ float g_qkv[(size_t)S_ * QKV_N];
__device__ float g_ctx[(size_t)S_ * E_];
__device__ __nv_bfloat16 g_xhi[(size_t)S_ * E_],     g_xlo[(size_t)S_ * E_];
__device__ __nv_bfloat16 g_wqhi[(size_t)QKV_N * E_], g_wqlo[(size_t)QKV_N * E_];
__device__ __nv_bfloat16 g_wohi[(size_t)E_ * E_],    g_wolo[(size_t)E_ * E_];
__device__ __nv_bfloat16 g_chi[(size_t)S_ * E_],     g_clo[(size_t)S_ * E_];

// ---------------- helpers --------------------------------------------------
__device__ __forceinline__ uint32_t smem_u32(const void* p) {
    return (uint32_t)__cvta_generic_to_shared(p);
}
__device__ __forceinline__ void cp16(uint32_t dst, const void* src) {
    asm volatile("cp.async.cg.shared.global [%0], [%1], 16;"
                 :: "r"(dst), "l"(src) : "memory");
}
__device__ __forceinline__ void ldm_x4(uint32_t* r, uint32_t addr) {
    asm volatile("ldmatrix.sync.aligned.m8n8.x4.shared.b16 {%0,%1,%2,%3}, [%4];"
                 : "=r"(r[0]), "=r"(r[1]), "=r"(r[2]), "=r"(r[3]) : "r"(addr));
}
__device__ __forceinline__ void mma_bf16(float* c, const uint32_t* a,
                                         uint32_t b0, uint32_t b1) {
    asm volatile(
        "mma.sync.aligned.m16n8k16.row.col.f32.bf16.bf16.f32 "
        "{%0,%1,%2,%3},{%4,%5,%6,%7},{%8,%9},{%0,%1,%2,%3};"
        : "+f"(c[0]), "+f"(c[1]), "+f"(c[2]), "+f"(c[3])
        : "r"(a[0]), "r"(a[1]), "r"(a[2]), "r"(a[3]), "r"(b0), "r"(b1));
}

// ---------------- fp32 -> (hi, lo) bf16 split ------------------------------
__global__ __launch_bounds__(256)
void conv_hilo(const float* __restrict__ src,
               __nv_bfloat16* __restrict__ hi,
               __nv_bfloat16* __restrict__ lo, int n4)
{
    int i = blockIdx.x * 256 + threadIdx.x;
    if (i >= n4) return;
    float4 v = ((const float4*)src)[i];
    float f[4] = {v.x, v.y, v.z, v.w};
    __nv_bfloat16 h[4], l[4];
    #pragma unroll
    for (int k = 0; k < 4; k++) {
        h[k] = __float2bfloat16(f[k]);
        l[k] = __float2bfloat16(f[k] - __bfloat162float(h[k]));
    }
    __nv_bfloat162* hp = (__nv_bfloat162*)hi;
    __nv_bfloat162* lp = (__nv_bfloat162*)lo;
    hp[2*i]   = __nv_bfloat162(h[0], h[1]);
    hp[2*i+1] = __nv_bfloat162(h[2], h[3]);
    lp[2*i]   = __nv_bfloat162(l[0], l[1]);
    lp[2*i+1] = __nv_bfloat162(l[2], l[3]);
}

// ---------------------------------------------------------------------------
// HMMA split-bf16 GEMM: 128x128 CTA, BK=32, 3-stage cp.async, 2 CTAs/SM.
// Load addresses hoisted out of the main loop (ALU trim).
// ---------------------------------------------------------------------------
#define STAGES     3
#define STAGE_B    32768
#define GEMM_SMEM  (STAGES * STAGE_B)

__global__ __launch_bounds__(256, 2)
void gemm_mma(int M, int N, int K,
              const __nv_bfloat16* __restrict__ Ahi,
              const __nv_bfloat16* __restrict__ Alo,
              const __nv_bfloat16* __restrict__ Bhi,
              const __nv_bfloat16* __restrict__ Blo,
              const float* __restrict__ bias,
              float* __restrict__ C)
{
    extern __shared__ char smem[];
    const uint32_t sbase = smem_u32(smem);
    const int tid  = threadIdx.x;
    const int wid  = tid >> 5, lane = tid & 31;
    const int bm   = blockIdx.y * 128, bn = blockIdx.x * 128;
    const int mi   = (wid >> 2) * 64;   // warp m offset
    const int ni   = (wid & 3) * 32;    // warp n offset
    const int NC   = K >> 5;            // chunks of 32

    // hoisted per-thread load addresses: 8 transfers (4 tiles x 2 reps)
    const __nv_bfloat16* srcp[8];
    uint32_t dsto[8];
    {
        const __nv_bfloat16* srcs[4] = {Ahi, Alo, Bhi, Blo};
        const int r0s[4] = {bm, bm, bn, bn};
        #pragma unroll
        for (int t4 = 0; t4 < 4; t4++)
            #pragma unroll
            for (int rep = 0; rep < 2; rep++) {
                int idx  = tid + rep * 256;
                int r    = idx >> 2, slot = idx & 3;
                srcp[t4 * 2 + rep] = srcs[t4] + (size_t)(r0s[t4] + r) * K + slot * 8;
                dsto[t4 * 2 + rep] = (uint32_t)(t4 * 8192 + r * 64 +
                                     16 * (slot ^ ((r >> 1) & 3)));
            }
    }

    auto load_chunk = [&](int kc, int st) {
        uint32_t stb = sbase + st * STAGE_B;
        const int ko = kc * 32;
        #pragma unroll
        for (int u = 0; u < 8; u++)
            cp16(stb + dsto[u], srcp[u] + ko);
        asm volatile("cp.async.commit_group;" ::: "memory");
    };

    float acc[4][4][4];
    #pragma unroll
    for (int i2 = 0; i2 < 4; i2++)
        #pragma unroll
        for (int j = 0; j < 4; j++)
            #pragma unroll
            for (int q = 0; q < 4; q++) acc[i2][j][q] = 0.f;

    load_chunk(0, 0);
    load_chunk(1, 1);

    // hoisted ldmatrix offsets (per ks, per fragment)
    uint32_t aoff[2][4], boff[2][2];
    #pragma unroll
    for (int ks = 0; ks < 2; ks++) {
        int slot = ks * 2 + (lane >> 4);
        #pragma unroll
        for (int i2 = 0; i2 < 4; i2++) {
            int r = mi + i2 * 16 + (lane & 15);
            aoff[ks][i2] = (uint32_t)(r * 64 + 16 * (slot ^ ((r >> 1) & 3)));
        }
        #pragma unroll
        for (int jp = 0; jp < 2; jp++) {
            int r = ni + jp * 16 + (lane & 15);
            boff[ks][jp] = (uint32_t)(r * 64 + 16 * (slot ^ ((r >> 1) & 3)));
        }
    }

    for (int c = 0; c < NC; ++c) {
        asm volatile("cp.async.wait_group 1;" ::: "memory");
        __syncthreads();
        if (c + 2 < NC) load_chunk(c + 2, (c + 2) % 3);

        uint32_t stb = sbase + (c % 3) * STAGE_B;
        #pragma unroll
        for (int ks = 0; ks < 2; ks++) {
            uint32_t ah[4][4], al[4][4];
            #pragma unroll
            for (int i2 = 0; i2 < 4; i2++) {
                ldm_x4(ah[i2], stb + 0    + aoff[ks][i2]);
                ldm_x4(al[i2], stb + 8192 + aoff[ks][i2]);
            }
            uint32_t bh[2][4], bl[2][4];
            #pragma unroll
            for (int jp = 0; jp < 2; jp++) {
                ldm_x4(bh[jp], stb + 16384 + boff[ks][jp]);
                ldm_x4(bl[jp], stb + 24576 + boff[ks][jp]);
            }
            #pragma unroll
            for (int i2 = 0; i2 < 4; i2++)
                #pragma unroll
                for (int jp = 0; jp < 2; jp++)
                    #pragma unroll
                    for (int sub = 0; sub < 2; sub++) {
                        float* cc = acc[i2][jp * 2 + sub];
                        mma_bf16(cc, ah[i2], bh[jp][sub], bh[jp][sub + 2]);
                        mma_bf16(cc, ah[i2], bl[jp][sub], bl[jp][sub + 2]);
                        mma_bf16(cc, al[i2], bh[jp][sub], bh[jp][sub + 2]);
                    }
        }
    }

    // epilogue: direct stores + bias
    const int row_l = lane >> 2, colq = (lane & 3) * 2;
    #pragma unroll
    for (int i2 = 0; i2 < 4; i2++) {
        int r0 = bm + mi + i2 * 16 + row_l;
        #pragma unroll
        for (int j = 0; j < 4; j++) {
            int cn = bn + ni + j * 8 + colq;
            float b0 = bias[cn], b1 = bias[cn + 1];
            float* cc = acc[i2][j];
            *(float2*)&C[(size_t)r0 * N + cn]       = make_float2(cc[0] + b0, cc[1] + b1);
            *(float2*)&C[(size_t)(r0 + 8) * N + cn] = make_float2(cc[2] + b0, cc[3] + b1);
        }
    }
}

// ---------------------------------------------------------------------------
// YaRN RoPE in-place on Q (heads 0..31) and K (heads 32..39) in g_qkv.
// ---------------------------------------------------------------------------
__global__ void rope_kernel(const int* __restrict__ pos_ids)
{
    const int i  = blockIdx.x;
    const int hh = blockIdx.y;
    const int k  = threadIdx.x;

    float freq = powf(10000.0f, -((float)(2 * k) / 64.0f));
    float wl   = 6.283185307179586f / freq;
    float t    = (wl - 128.0f) / (4096.0f - 128.0f);
    t = fminf(fmaxf(t, 0.0f), 1.0f);
    float eff  = freq * (1.0f - t) + (freq * 0.5f) * t;
    float conc = 0.1f * logf(2.0f) + 1.0f;
    float ang  = (float)pos_ids[i] * eff * conc;
    float sv = sinf(ang), cv = cosf(ang);

    float* p = g_qkv + (size_t)i * QKV_N + hh * DH;
    float x1 = p[k], x2 = p[k + 32];
    p[k]      = x1 * cv - x2 * sv;
    p[k + 32] = x2 * cv + x1 * sv;
}

// ---------------------------------------------------------------------------
// Windowed attention with sink. One block = (query i, kv-group g), computes
// all 4 q-heads of the group off one K/V staging (R3 version - measured good).
// ---------------------------------------------------------------------------
__global__ __launch_bounds__(128)
void attn_kernel(const float* __restrict__ sinks)
{
    const int i   = blockIdx.x;
    const int g   = blockIdx.y;
    const int tid = threadIdx.x;
    const int w   = tid >> 5, l = tid & 31;

    __shared__ float qs[4 * 64];
    __shared__ float Ks[128 * 65];
    __shared__ float ps[4 * 132];
    __shared__ float mh[4], ih[4];
    __shared__ float cp4[128][4];

    const int jstart = max(0, i - (SW_ - 1));
    const int nk     = i - jstart + 1;

    for (int e = tid; e < 256; e += 128) {
        int h = e >> 6, d = e & 63;
        qs[e] = g_qkv[(size_t)i * QKV_N + (g * 4 + h) * DH + d];
    }
    const int kofs = (NH + g) * DH;
    for (int e = tid; e < nk * 64; e += 128) {
        int j = e >> 6, d = e & 63;
        Ks[j * 65 + d] = g_qkv[(size_t)(jstart + j) * QKV_N + kofs + d];
    }
    __syncthreads();

    // scores: thread tid = key j, all 4 heads
    float s[4] = {-INFINITY, -INFINITY, -INFINITY, -INFINITY};
    if (tid < nk) {
        float a0 = 0.f, a1 = 0.f, a2 = 0.f, a3 = 0.f;
        #pragma unroll
        for (int d = 0; d < 64; d++) {
            float kv = Ks[tid * 65 + d];
            a0 += qs[d] * kv; a1 += qs[64 + d] * kv;
            a2 += qs[128 + d] * kv; a3 += qs[192 + d] * kv;
        }
        s[0] = a0 * 0.125f; s[1] = a1 * 0.125f;
        s[2] = a2 * 0.125f; s[3] = a3 * 0.125f;
    }
    #pragma unroll
    for (int h = 0; h < 4; h++) ps[h * 132 + tid] = s[h];
    __syncthreads();

    // warp w reduces max of head w
    {
        float m = fmaxf(fmaxf(ps[w * 132 + l], ps[w * 132 + l + 32]),
                        fmaxf(ps[w * 132 + l + 64], ps[w * 132 + l + 96]));
        #pragma unroll
        for (int off = 16; off > 0; off >>= 1)
            m = fmaxf(m, __shfl_xor_sync(0xffffffffu, m, off));
        if (l == 0) mh[w] = fmaxf(m, sinks[g * 4 + w]);
    }
    __syncthreads();

    #pragma unroll
    for (int h = 0; h < 4; h++) {
        float p = (tid < nk) ? __expf(s[h] - mh[h]) : 0.f;
        ps[h * 132 + tid] = p;
    }
    __syncthreads();

    // warp w reduces sum of head w
    {
        float sm = ps[w * 132 + l] + ps[w * 132 + l + 32] +
                   ps[w * 132 + l + 64] + ps[w * 132 + l + 96];
        #pragma unroll
        for (int off = 16; off > 0; off >>= 1)
            sm += __shfl_xor_sync(0xffffffffu, sm, off);
        if (l == 0) ih[w] = 1.f / (sm + __expf(sinks[g * 4 + w] - mh[w]));
    }

    // stage V (reuse Ks)
    const int vofs = (NH + NG + g) * DH;
    for (int e = tid; e < nk * 64; e += 128) {
        int j = e >> 6, d = e & 63;
        Ks[j * 65 + d] = g_qkv[(size_t)(jstart + j) * QKV_N + vofs + d];
    }
    __syncthreads();

    const int d    = tid & 63;
    const int half = tid >> 6;
    float acc[4] = {0.f, 0.f, 0.f, 0.f};
    for (int j = half; j < nk; j += 2) {
        float v = Ks[j * 65 + d];
        #pragma unroll
        for (int h = 0; h < 4; h++) acc[h] += ps[h * 132 + j] * v;
    }
    #pragma unroll
    for (int h = 0; h < 4; h++) cp4[tid][h] = acc[h];
    __syncthreads();
    if (tid < 64) {
        #pragma unroll
        for (int h = 0; h < 4; h++) {
            float v = (cp4[tid][h] + cp4[64 + tid][h]) * ih[h];
            g_ctx[(size_t)i * E_ + (g * 4 + h) * DH + tid] = v;
        }
    }
}

// ---------------------------------------------------------------------------
extern "C" void kernel_launch(void* const* d_in, const int* in_sizes, int n_in,
                              void* d_out, int out_size)
{
    const float* x     = (const float*)d_in[0];
    const int*   pos   = (const int*)  d_in[1];
    const float* Wqkv  = (const float*)d_in[3];
    const float* bqkv  = (const float*)d_in[4];
    const float* Wout  = (const float*)d_in[5];
    const float* bout  = (const float*)d_in[6];
    const float* sinks = (const float*)d_in[7];
    float* out = (float*)d_out;

    float *qkv_p = nullptr, *ctx_p = nullptr;
    __nv_bfloat16 *xhi, *xlo, *wqhi, *wqlo, *wohi, *wolo, *chi, *clo;
    cudaGetSymbolAddress((void**)&qkv_p, g_qkv);
    cudaGetSymbolAddress((void**)&ctx_p, g_ctx);
    cudaGetSymbolAddress((void**)&xhi,  g_xhi);  cudaGetSymbolAddress((void**)&xlo,  g_xlo);
    cudaGetSymbolAddress((void**)&wqhi, g_wqhi); cudaGetSymbolAddress((void**)&wqlo, g_wqlo);
    cudaGetSymbolAddress((void**)&wohi, g_wohi); cudaGetSymbolAddress((void**)&wolo, g_wolo);
    cudaGetSymbolAddress((void**)&chi,  g_chi);  cudaGetSymbolAddress((void**)&clo,  g_clo);

    cudaFuncSetAttribute(gemm_mma, cudaFuncAttributeMaxDynamicSharedMemorySize, GEMM_SMEM);

    // 0) split inputs into bf16 hi/lo
    {
        int n4 = (S_ * E_) / 4;
        conv_hilo<<<(n4 + 255) / 256, 256>>>(x, xhi, xlo, n4);
        n4 = (QKV_N * E_) / 4;
        conv_hilo<<<(n4 + 255) / 256, 256>>>(Wqkv, wqhi, wqlo, n4);
        n4 = (E_ * E_) / 4;
        conv_hilo<<<(n4 + 255) / 256, 256>>>(Wout, wohi, wolo, n4);
    }

    // 1) qkv = x @ Wqkv^T + bqkv
    gemm_mma<<<dim3(QKV_N / 128, S_ / 128), 256, GEMM_SMEM>>>(
        S_, QKV_N, E_, xhi, xlo, wqhi, wqlo, bqkv, qkv_p);

    // 2) RoPE
    rope_kernel<<<dim3(S_, NH + NG), 32>>>(pos);

    // 3) windowed sink attention (grouped, per-query)
    attn_kernel<<<dim3(S_, NG), 128>>>(sinks);

    // 4) ctx -> bf16 hi/lo, then out = ctx @ Wout^T + bout
    {
        int n4 = (S_ * E_) / 4;
        conv_hilo<<<(n4 + 255) / 256, 256>>>(ctx_p, chi, clo, n4);
    }
    gemm_mma<<<dim3(E_ / 128, S_ / 128), 256, GEMM_SMEM>>>(
        S_, E_, E_, chi, clo, wohi, wolo, bout, out);
}

// round 6
// speedup vs baseline: 1.4428x; 1.2252x over previous
#include <cuda_runtime.h>
#include <cuda_bf16.h>
#include <math.h>
#include <stdint.h>

#define S_     2048
#define E_     2048
#define NH     32
#define NG     8
#define DH     64
#define QKV_N  3072   /* (H + 2G) * D */
#define SW_    128
#define ATQ    8      /* queries per attention block */

// ---------------- scratch (__device__ globals; no allocs allowed) ----------
__device__ float g_qkv[(size_t)S_ * QKV_N];
__device__ float g_ctx[(size_t)S_ * E_];
__device__ __nv_bfloat16 g_xhi[(size_t)S_ * E_],     g_xlo[(size_t)S_ * E_];
__device__ __nv_bfloat16 g_wqhi[(size_t)QKV_N * E_], g_wqlo[(size_t)QKV_N * E_];
__device__ __nv_bfloat16 g_wohi[(size_t)E_ * E_],    g_wolo[(size_t)E_ * E_];
__device__ __nv_bfloat16 g_chi[(size_t)S_ * E_],     g_clo[(size_t)S_ * E_];

// ---------------- helpers --------------------------------------------------
__device__ __forceinline__ uint32_t smem_u32(const void* p) {
    return (uint32_t)__cvta_generic_to_shared(p);
}
__device__ __forceinline__ void cp16(uint32_t dst, const void* src) {
    asm volatile("cp.async.cg.shared.global [%0], [%1], 16;"
                 :: "r"(dst), "l"(src) : "memory");
}
__device__ __forceinline__ void ldm_x4(uint32_t* r, uint32_t addr) {
    asm volatile("ldmatrix.sync.aligned.m8n8.x4.shared.b16 {%0,%1,%2,%3}, [%4];"
                 : "=r"(r[0]), "=r"(r[1]), "=r"(r[2]), "=r"(r[3]) : "r"(addr));
}
__device__ __forceinline__ void mma_bf16(float* c, const uint32_t* a,
                                         uint32_t b0, uint32_t b1) {
    asm volatile(
        "mma.sync.aligned.m16n8k16.row.col.f32.bf16.bf16.f32 "
        "{%0,%1,%2,%3},{%4,%5,%6,%7},{%8,%9},{%0,%1,%2,%3};"
        : "+f"(c[0]), "+f"(c[1]), "+f"(c[2]), "+f"(c[3])
        : "r"(a[0]), "r"(a[1]), "r"(a[2]), "r"(a[3]), "r"(b0), "r"(b1));
}

// ---------------- fp32 -> (hi, lo) bf16 split ------------------------------
__global__ __launch_bounds__(256)
void conv_hilo(const float* __restrict__ src,
               __nv_bfloat16* __restrict__ hi,
               __nv_bfloat16* __restrict__ lo, int n4)
{
    int i = blockIdx.x * 256 + threadIdx.x;
    if (i >= n4) return;
    float4 v = ((const float4*)src)[i];
    float f[4] = {v.x, v.y, v.z, v.w};
    __nv_bfloat16 h[4], l[4];
    #pragma unroll
    for (int k = 0; k < 4; k++) {
        h[k] = __float2bfloat16(f[k]);
        l[k] = __float2bfloat16(f[k] - __bfloat162float(h[k]));
    }
    __nv_bfloat162* hp = (__nv_bfloat162*)hi;
    __nv_bfloat162* lp = (__nv_bfloat162*)lo;
    hp[2*i]   = __nv_bfloat162(h[0], h[1]);
    hp[2*i+1] = __nv_bfloat162(h[2], h[3]);
    lp[2*i]   = __nv_bfloat162(l[0], l[1]);
    lp[2*i+1] = __nv_bfloat162(l[2], l[3]);
}

// ---------------------------------------------------------------------------
// HMMA split-bf16 GEMM: 128x128 CTA, BK=32, 3-stage cp.async, 2 CTAs/SM.
// ---------------------------------------------------------------------------
#define STAGES     3
#define STAGE_B    32768
#define GEMM_SMEM  (STAGES * STAGE_B)

__global__ __launch_bounds__(256, 2)
void gemm_mma(int M, int N, int K,
              const __nv_bfloat16* __restrict__ Ahi,
              const __nv_bfloat16* __restrict__ Alo,
              const __nv_bfloat16* __restrict__ Bhi,
              const __nv_bfloat16* __restrict__ Blo,
              const float* __restrict__ bias,
              float* __restrict__ C)
{
    extern __shared__ char smem[];
    const uint32_t sbase = smem_u32(smem);
    const int tid  = threadIdx.x;
    const int wid  = tid >> 5, lane = tid & 31;
    const int bm   = blockIdx.y * 128, bn = blockIdx.x * 128;
    const int mi   = (wid >> 2) * 64;
    const int ni   = (wid & 3) * 32;
    const int NC   = K >> 5;

    const __nv_bfloat16* srcp[8];
    uint32_t dsto[8];
    {
        const __nv_bfloat16* srcs[4] = {Ahi, Alo, Bhi, Blo};
        const int r0s[4] = {bm, bm, bn, bn};
        #pragma unroll
        for (int t4 = 0; t4 < 4; t4++)
            #pragma unroll
            for (int rep = 0; rep < 2; rep++) {
                int idx  = tid + rep * 256;
                int r    = idx >> 2, slot = idx & 3;
                srcp[t4 * 2 + rep] = srcs[t4] + (size_t)(r0s[t4] + r) * K + slot * 8;
                dsto[t4 * 2 + rep] = (uint32_t)(t4 * 8192 + r * 64 +
                                     16 * (slot ^ ((r >> 1) & 3)));
            }
    }

    auto load_chunk = [&](int kc, int st) {
        uint32_t stb = sbase + st * STAGE_B;
        const int ko = kc * 32;
        #pragma unroll
        for (int u = 0; u < 8; u++)
            cp16(stb + dsto[u], srcp[u] + ko);
        asm volatile("cp.async.commit_group;" ::: "memory");
    };

    float acc[4][4][4];
    #pragma unroll
    for (int i2 = 0; i2 < 4; i2++)
        #pragma unroll
        for (int j = 0; j < 4; j++)
            #pragma unroll
            for (int q = 0; q < 4; q++) acc[i2][j][q] = 0.f;

    load_chunk(0, 0);
    load_chunk(1, 1);

    uint32_t aoff[2][4], boff[2][2];
    #pragma unroll
    for (int ks = 0; ks < 2; ks++) {
        int slot = ks * 2 + (lane >> 4);
        #pragma unroll
        for (int i2 = 0; i2 < 4; i2++) {
            int r = mi + i2 * 16 + (lane & 15);
            aoff[ks][i2] = (uint32_t)(r * 64 + 16 * (slot ^ ((r >> 1) & 3)));
        }
        #pragma unroll
        for (int jp = 0; jp < 2; jp++) {
            int r = ni + jp * 16 + (lane & 15);
            boff[ks][jp] = (uint32_t)(r * 64 + 16 * (slot ^ ((r >> 1) & 3)));
        }
    }

    for (int c = 0; c < NC; ++c) {
        asm volatile("cp.async.wait_group 1;" ::: "memory");
        __syncthreads();
        if (c + 2 < NC) load_chunk(c + 2, (c + 2) % 3);

        uint32_t stb = sbase + (c % 3) * STAGE_B;
        #pragma unroll
        for (int ks = 0; ks < 2; ks++) {
            uint32_t ah[4][4], al[4][4];
            #pragma unroll
            for (int i2 = 0; i2 < 4; i2++) {
                ldm_x4(ah[i2], stb + 0    + aoff[ks][i2]);
                ldm_x4(al[i2], stb + 8192 + aoff[ks][i2]);
            }
            uint32_t bh[2][4], bl[2][4];
            #pragma unroll
            for (int jp = 0; jp < 2; jp++) {
                ldm_x4(bh[jp], stb + 16384 + boff[ks][jp]);
                ldm_x4(bl[jp], stb + 24576 + boff[ks][jp]);
            }
            #pragma unroll
            for (int i2 = 0; i2 < 4; i2++)
                #pragma unroll
                for (int jp = 0; jp < 2; jp++)
                    #pragma unroll
                    for (int sub = 0; sub < 2; sub++) {
                        float* cc = acc[i2][jp * 2 + sub];
                        mma_bf16(cc, ah[i2], bh[jp][sub], bh[jp][sub + 2]);
                        mma_bf16(cc, ah[i2], bl[jp][sub], bl[jp][sub + 2]);
                        mma_bf16(cc, al[i2], bh[jp][sub], bh[jp][sub + 2]);
                    }
        }
    }

    const int row_l = lane >> 2, colq = (lane & 3) * 2;
    #pragma unroll
    for (int i2 = 0; i2 < 4; i2++) {
        int r0 = bm + mi + i2 * 16 + row_l;
        #pragma unroll
        for (int j = 0; j < 4; j++) {
            int cn = bn + ni + j * 8 + colq;
            float b0 = bias[cn], b1 = bias[cn + 1];
            float* cc = acc[i2][j];
            *(float2*)&C[(size_t)r0 * N + cn]       = make_float2(cc[0] + b0, cc[1] + b1);
            *(float2*)&C[(size_t)(r0 + 8) * N + cn] = make_float2(cc[2] + b0, cc[3] + b1);
        }
    }
}

// ---------------------------------------------------------------------------
// YaRN RoPE in-place on Q (heads 0..31) and K (heads 32..39) in g_qkv.
// ---------------------------------------------------------------------------
__global__ void rope_kernel(const int* __restrict__ pos_ids)
{
    const int i  = blockIdx.x;
    const int hh = blockIdx.y;
    const int k  = threadIdx.x;

    float freq = powf(10000.0f, -((float)(2 * k) / 64.0f));
    float wl   = 6.283185307179586f / freq;
    float t    = (wl - 128.0f) / (4096.0f - 128.0f);
    t = fminf(fmaxf(t, 0.0f), 1.0f);
    float eff  = freq * (1.0f - t) + (freq * 0.5f) * t;
    float conc = 0.1f * logf(2.0f) + 1.0f;
    float ang  = (float)pos_ids[i] * eff * conc;
    float sv = sinf(ang), cv = cosf(ang);

    float* p = g_qkv + (size_t)i * QKV_N + hh * DH;
    float x1 = p[k], x2 = p[k + 32];
    p[k]      = x1 * cv - x2 * sv;
    p[k + 32] = x2 * cv + x1 * sv;
}

// ---------------------------------------------------------------------------
// Windowed sink attention, warp-per-query, 8-query tile per block.
// Block = (q-tile, kv-group). K/V window (<=135 keys) + Q staged once via
// float4; after one __syncthreads each warp handles one query with 4 heads:
// scores (lane = key), softmax via shfl, AV (lane = dims d, d+32).
// smem strides: K/V 68 floats (float4-aligned), ps 144.
// ---------------------------------------------------------------------------
#define AKV   136
#define ASTR  68
#define ATT_SMEM_FLOATS (2 * AKV * ASTR + ATQ * 4 * ASTR + ATQ * 4 * 144)
#define ATT_SMEM_BYTES  (ATT_SMEM_FLOATS * 4)

__global__ __launch_bounds__(256)
void attn_kernel(const float* __restrict__ sinks)
{
    extern __shared__ float sm[];
    float* Ks = sm;                         // [136][68]
    float* Vs = Ks + AKV * ASTR;            // [136][68]
    float* Qs = Vs + AKV * ASTR;            // [8][4][68]
    float* ps = Qs + ATQ * 4 * ASTR;        // [8][4][144]

    const int q0  = blockIdx.x * ATQ;
    const int g   = blockIdx.y;
    const int tid = threadIdx.x;
    const int w   = tid >> 5, lane = tid & 31;

    const int j0 = max(0, q0 - (SW_ - 1));
    const int nk = q0 + ATQ - j0;           // <= 135

    // ---- stage K, V, Q via float4 ----
    const float4* src = (const float4*)g_qkv;
    const int rowq = QKV_N / 4;             // 768 float4 per row
    for (int e = tid; e < nk * 16; e += 256) {
        int j = e >> 4, d4 = e & 15;
        ((float4*)(Ks + j * ASTR))[d4] = src[(size_t)(j0 + j) * rowq + (NH + g) * 16 + d4];
        ((float4*)(Vs + j * ASTR))[d4] = src[(size_t)(j0 + j) * rowq + (NH + NG + g) * 16 + d4];
    }
    for (int e = tid; e < ATQ * 4 * 16; e += 256) {
        int q = e >> 6, h = (e >> 4) & 3, d4 = e & 15;
        ((float4*)(Qs + (q * 4 + h) * ASTR))[d4] =
            src[(size_t)(q0 + q) * rowq + (g * 4 + h) * 16 + d4];
    }
    __syncthreads();

    // ---- per-warp: query i = q0 + w ----
    const int i  = q0 + w;
    const int hi = i - j0;                            // last valid local key
    const int lo = (hi - (SW_ - 1)) > 0 ? (hi - (SW_ - 1)) : 0;

    float s[5][4];
    #pragma unroll
    for (int kk = 0; kk < 5; kk++)
        #pragma unroll
        for (int h = 0; h < 4; h++) s[kk][h] = -INFINITY;

    const float4* Q40 = (const float4*)(Qs + (w * 4 + 0) * ASTR);
    const float4* Q41 = (const float4*)(Qs + (w * 4 + 1) * ASTR);
    const float4* Q42 = (const float4*)(Qs + (w * 4 + 2) * ASTR);
    const float4* Q43 = (const float4*)(Qs + (w * 4 + 3) * ASTR);

    #pragma unroll
    for (int kk = 0; kk < 5; kk++) {
        int j = kk * 32 + lane;
        if (j >= lo && j <= hi) {
            const float4* K4 = (const float4*)(Ks + j * ASTR);
            float a0 = 0.f, a1 = 0.f, a2 = 0.f, a3 = 0.f;
            #pragma unroll
            for (int d4 = 0; d4 < 16; d4++) {
                float4 kv = K4[d4];
                float4 v0 = Q40[d4], v1 = Q41[d4], v2 = Q42[d4], v3 = Q43[d4];
                a0 += kv.x * v0.x + kv.y * v0.y + kv.z * v0.z + kv.w * v0.w;
                a1 += kv.x * v1.x + kv.y * v1.y + kv.z * v1.z + kv.w * v1.w;
                a2 += kv.x * v2.x + kv.y * v2.y + kv.z * v2.z + kv.w * v2.w;
                a3 += kv.x * v3.x + kv.y * v3.y + kv.z * v3.z + kv.w * v3.w;
            }
            s[kk][0] = a0 * 0.125f; s[kk][1] = a1 * 0.125f;
            s[kk][2] = a2 * 0.125f; s[kk][3] = a3 * 0.125f;
        }
    }

    // ---- softmax per head (warp-local, shfl) ----
    #pragma unroll
    for (int h = 0; h < 4; h++) {
        const float sink = sinks[g * 4 + h];
        float m = -INFINITY;
        #pragma unroll
        for (int kk = 0; kk < 5; kk++) m = fmaxf(m, s[kk][h]);
        #pragma unroll
        for (int off = 16; off > 0; off >>= 1)
            m = fmaxf(m, __shfl_xor_sync(0xffffffffu, m, off));
        m = fmaxf(m, sink);

        float p[5], sum = 0.f;
        #pragma unroll
        for (int kk = 0; kk < 5; kk++) {
            p[kk] = __expf(s[kk][h] - m);   // -inf -> 0
            sum += p[kk];
        }
        #pragma unroll
        for (int off = 16; off > 0; off >>= 1)
            sum += __shfl_xor_sync(0xffffffffu, sum, off);
        const float inv = 1.f / (sum + __expf(sink - m));

        float* pr = ps + (w * 4 + h) * 144;
        #pragma unroll
        for (int kk = 0; kk < 5; kk++) {
            int j = kk * 32 + lane;
            if (j < AKV) pr[j] = p[kk] * inv;
        }
    }
    __syncwarp();

    // ---- AV: lane owns dims (lane, lane+32) for all 4 heads ----
    float accA[4], accB[4];
    #pragma unroll
    for (int h = 0; h < 4; h++) { accA[h] = 0.f; accB[h] = 0.f; }
    const float* pr0 = ps + (w * 4 + 0) * 144;
    const float* pr1 = ps + (w * 4 + 1) * 144;
    const float* pr2 = ps + (w * 4 + 2) * 144;
    const float* pr3 = ps + (w * 4 + 3) * 144;
    for (int j = lo; j <= hi; j++) {
        float v0 = Vs[j * ASTR + lane];
        float v1 = Vs[j * ASTR + lane + 32];
        float p0 = pr0[j], p1 = pr1[j], p2 = pr2[j], p3 = pr3[j];
        accA[0] += p0 * v0; accB[0] += p0 * v1;
        accA[1] += p1 * v0; accB[1] += p1 * v1;
        accA[2] += p2 * v0; accB[2] += p2 * v1;
        accA[3] += p3 * v0; accB[3] += p3 * v1;
    }
    #pragma unroll
    for (int h = 0; h < 4; h++) {
        g_ctx[(size_t)i * E_ + (g * 4 + h) * DH + lane]      = accA[h];
        g_ctx[(size_t)i * E_ + (g * 4 + h) * DH + lane + 32] = accB[h];
    }
}

// ---------------------------------------------------------------------------
extern "C" void kernel_launch(void* const* d_in, const int* in_sizes, int n_in,
                              void* d_out, int out_size)
{
    const float* x     = (const float*)d_in[0];
    const int*   pos   = (const int*)  d_in[1];
    const float* Wqkv  = (const float*)d_in[3];
    const float* bqkv  = (const float*)d_in[4];
    const float* Wout  = (const float*)d_in[5];
    const float* bout  = (const float*)d_in[6];
    const float* sinks = (const float*)d_in[7];
    float* out = (float*)d_out;

    float *qkv_p = nullptr, *ctx_p = nullptr;
    __nv_bfloat16 *xhi, *xlo, *wqhi, *wqlo, *wohi, *wolo, *chi, *clo;
    cudaGetSymbolAddress((void**)&qkv_p, g_qkv);
    cudaGetSymbolAddress((void**)&ctx_p, g_ctx);
    cudaGetSymbolAddress((void**)&xhi,  g_xhi);  cudaGetSymbolAddress((void**)&xlo,  g_xlo);
    cudaGetSymbolAddress((void**)&wqhi, g_wqhi); cudaGetSymbolAddress((void**)&wqlo, g_wqlo);
    cudaGetSymbolAddress((void**)&wohi, g_wohi); cudaGetSymbolAddress((void**)&wolo, g_wolo);
    cudaGetSymbolAddress((void**)&chi,  g_chi);  cudaGetSymbolAddress((void**)&clo,  g_clo);

    cudaFuncSetAttribute(gemm_mma, cudaFuncAttributeMaxDynamicSharedMemorySize, GEMM_SMEM);
    cudaFuncSetAttribute(attn_kernel, cudaFuncAttributeMaxDynamicSharedMemorySize, ATT_SMEM_BYTES);

    // 0) split inputs into bf16 hi/lo
    {
        int n4 = (S_ * E_) / 4;
        conv_hilo<<<(n4 + 255) / 256, 256>>>(x, xhi, xlo, n4);
        n4 = (QKV_N * E_) / 4;
        conv_hilo<<<(n4 + 255) / 256, 256>>>(Wqkv, wqhi, wqlo, n4);
        n4 = (E_ * E_) / 4;
        conv_hilo<<<(n4 + 255) / 256, 256>>>(Wout, wohi, wolo, n4);
    }

    // 1) qkv = x @ Wqkv^T + bqkv
    gemm_mma<<<dim3(QKV_N / 128, S_ / 128), 256, GEMM_SMEM>>>(
        S_, QKV_N, E_, xhi, xlo, wqhi, wqlo, bqkv, qkv_p);

    // 2) RoPE
    rope_kernel<<<dim3(S_, NH + NG), 32>>>(pos);

    // 3) windowed sink attention (warp-per-query, 8-query tiles)
    attn_kernel<<<dim3(S_ / ATQ, NG), 256, ATT_SMEM_BYTES>>>(sinks);

    // 4) ctx -> bf16 hi/lo, then out = ctx @ Wout^T + bout
    {
        int n4 = (S_ * E_) / 4;
        conv_hilo<<<(n4 + 255) / 256, 256>>>(ctx_p, chi, clo, n4);
    }
    gemm_mma<<<dim3(E_ / 128, S_ / 128), 256, GEMM_SMEM>>>(
        S_, E_, E_, chi, clo, wohi, wolo, bout, out);
}